// round 2
// baseline (speedup 1.0000x reference)
#include <cuda_runtime.h>

#define N_NODES 2048
#define NGR 512
#define NGRAPH 4
#define NEDGE 32768
#define DIM 128
#define HEADS 4
#define GRID_PTS 500
#define NQ 20
#define NRG 12   // 3 readouts x 4 graphs

// ---------------- device scratch (no allocations allowed) ----------------
__device__ float g_xh[N_NODES*DIM];
__device__ float g_als[N_NODES*HEADS];
__device__ float g_ald[N_NODES*HEADS];
__device__ float g_cur1[N_NODES*DIM];
__device__ float g_cur2[N_NODES*DIM];
__device__ int   g_deg[N_NODES];
__device__ int   g_cursor[N_NODES];
__device__ int   g_off[N_NODES+1];
__device__ int   g_adj[NEDGE];
__device__ float g_stats[NRG*DIM*4];   // per (rg,d): {mn_centered, step, c2, mid}
__device__ float g_pool[NRG*DIM];      // pool-weighted readout vector
__device__ float g_dens[NRG*DIM*512];  // [rg][d][512] (500 valid)
__device__ float g_kf[NRG*DIM*NQ];
__device__ float g_acc[NGRAPH*32];

__device__ __forceinline__ float ex2(float x){
    float y; asm("ex2.approx.ftz.f32 %0, %1;" : "=f"(y) : "f"(x)); return y;
}

// ---------------- CSR build ----------------
__global__ void k_zero(){
    int t = blockIdx.x*blockDim.x + threadIdx.x;
    if (t < N_NODES){ g_deg[t]=0; g_cursor[t]=0; }
    if (t < NGRAPH*32) g_acc[t]=0.f;
}
__global__ void k_count(const int* __restrict__ ei){
    int e = blockIdx.x*blockDim.x + threadIdx.x;
    if (e < NEDGE) atomicAdd(&g_deg[ei[NEDGE+e]], 1);
}
__global__ void k_scan(){
    int l = threadIdx.x;         // one warp
    int base = l*64;
    int s = 0;
    for (int k=0;k<64;k++) s += g_deg[base+k];
    int x = s;
    for (int o=1;o<32;o<<=1){ int v=__shfl_up_sync(0xffffffffu,x,o); if (l>=o) x+=v; }
    int run = x - s;
    for (int k=0;k<64;k++){ g_off[base+k]=run; run += g_deg[base+k]; }
    if (l==31) g_off[N_NODES] = run;
}
__global__ void k_fill(const int* __restrict__ ei){
    int e = blockIdx.x*blockDim.x + threadIdx.x;
    if (e < NEDGE){
        int d = ei[NEDGE+e];
        int pos = atomicAdd(&g_cursor[d],1);
        g_adj[g_off[d]+pos] = ei[e];
    }
}

// ---------------- GAT: xh = cur @ W ; al_s, al_d ----------------
__global__ void k_lin(const float* __restrict__ x, int use_cur1,
                      const float* __restrict__ W,
                      const float* __restrict__ as_,
                      const float* __restrict__ ad_){
    const float* cur = use_cur1 ? g_cur1 : x;
    int n = blockIdx.x, t = threadIdx.x;
    __shared__ float srow[DIM];
    srow[t] = cur[n*DIM + t];
    __syncthreads();
    float acc = 0.f;
    #pragma unroll 16
    for (int k=0;k<DIM;k++) acc = fmaf(srow[k], W[k*DIM + t], acc);
    g_xh[n*DIM + t] = acc;
    int h = t>>5;
    float ps = acc*as_[t];   // as_[h*32+c], t==h*32+c
    float pd = acc*ad_[t];
    for (int o=16;o;o>>=1){ ps += __shfl_xor_sync(0xffffffffu,ps,o);
                            pd += __shfl_xor_sync(0xffffffffu,pd,o); }
    if ((t&31)==0){ g_als[n*HEADS+h]=ps; g_ald[n*HEADS+h]=pd; }
}

// ---------------- GAT attention + aggregation (per node, gather) ----------------
__global__ void k_att(const float* __restrict__ bias, int layer){
    float* out = layer ? g_cur2 : g_cur1;
    int relu = (layer==0);
    int n = blockIdx.x, t = threadIdx.x;
    int w = t>>5, lane = t&31;
    int beg = g_off[n], deg = g_off[n+1]-beg;
    __shared__ float smax[HEADS], sinv[HEADS];
    float aldn = g_ald[n*HEADS + w];
    float m = -1e30f;
    for (int i=lane;i<deg+1;i+=32){
        int s = (i<deg) ? g_adj[beg+i] : n;
        float z = g_als[s*HEADS+w] + aldn;
        z = (z>0.f) ? z : 0.2f*z;
        m = fmaxf(m, z);
    }
    for (int o=16;o;o>>=1) m = fmaxf(m, __shfl_xor_sync(0xffffffffu,m,o));
    float sum = 0.f;
    for (int i=lane;i<deg+1;i+=32){
        int s = (i<deg) ? g_adj[beg+i] : n;
        float z = g_als[s*HEADS+w] + aldn;
        z = (z>0.f) ? z : 0.2f*z;
        sum += __expf(z - m);
    }
    for (int o=16;o;o>>=1) sum += __shfl_xor_sync(0xffffffffu,sum,o);
    if (lane==0){ smax[w]=m; sinv[w]=1.f/(sum + 1e-16f); }
    __syncthreads();
    float m2 = smax[w], inv = sinv[w];
    float acc = 0.f;
    for (int i=0;i<deg+1;i++){
        int s = (i<deg) ? g_adj[beg+i] : n;
        float z = g_als[s*HEADS+w] + aldn;
        z = (z>0.f) ? z : 0.2f*z;
        float alpha = __expf(z - m2)*inv;
        acc = fmaf(alpha, g_xh[s*DIM + t], acc);
    }
    acc += bias[t];
    if (relu) acc = fmaxf(acc, 0.f);
    out[n*DIM + t] = acc;
}

// ---------------- per (rg,d) stats + pooling ----------------
__global__ void k_stats(const float* __restrict__ x, const float* __restrict__ pw){
    int rg = blockIdx.x; int g = rg & 3; int ro = rg >> 2;
    const float* cur = (ro==0) ? x : (ro==1) ? g_cur1 : g_cur2;
    int t = threadIdx.x;             // 512
    int d = t & 127, c = t >> 7;     // 4 chunks of 128 nodes
    float mn=1e30f, mx=-1e30f, s1=0.f, s2=0.f;
    const float* base = cur + (size_t)(g*NGR)*DIM + d;
    for (int n=c*128; n<c*128+128; n++){
        float v = base[(size_t)n*DIM];
        mn = fminf(mn,v); mx = fmaxf(mx,v); s1 += v; s2 = fmaf(v,v,s2);
    }
    __shared__ float red[512];
    red[t]=s1; __syncthreads();
    if (c==0) s1 = red[d]+red[d+128]+red[d+256]+red[d+384];
    __syncthreads();
    red[t]=s2; __syncthreads();
    if (c==0) s2 = red[d]+red[d+128]+red[d+256]+red[d+384];
    __syncthreads();
    red[t]=mn; __syncthreads();
    if (c==0) mn = fminf(fminf(red[d],red[d+128]),fminf(red[d+256],red[d+384]));
    __syncthreads();
    red[t]=mx; __syncthreads();
    if (c==0) mx = fmaxf(fmaxf(red[d],red[d+128]),fmaxf(red[d+256],red[d+384]));
    if (c==0){
        float mean = s1*(1.f/512.f);
        float var  = fmaxf(s2*(1.f/512.f) - mean*mean, 0.f);
        float stdv = sqrtf(var) + 3.3333333e-9f;        // +1e-8/3
        float h    = 0.30440506f*stdv;                   // 1.06*512^-0.2
        float c2   = -0.72134752f/(h*h);                 // -0.5*log2(e)/h^2
        float mnA = mn - 1e-6f, mxA = mx + 1e-6f;
        float step = (mxA - mnA)*(1.f/499.f);
        float mid  = 0.5f*(mnA + mxA);
        float* st = &g_stats[(rg*DIM + d)*4];
        st[0] = mnA - mid; st[1] = step; st[2] = c2; st[3] = mid;
        g_pool[rg*DIM + d] = pw[0]*mean + pw[1]*mx;
    }
}

// ---------------- KDE density (the hot kernel, MUFU-bound) ----------------
// grid: 768 blocks = 4 p-blocks x 16 d-blocks x 12 rg. Block: 256 threads.
// thread: one dim (dl = t&7), 4 grid points. dens[rg][d][p] = sum_n 2^{c2(gp-x)^2}
__global__ void __launch_bounds__(256,6) k_dens(const float* __restrict__ x){
    int b = blockIdx.x;
    int pblk = b & 3, dblk = (b>>2) & 15, rg = b >> 6;
    int g = rg & 3, ro = rg >> 2;
    const float* cur = (ro==0) ? x : (ro==1) ? g_cur1 : g_cur2;
    int t = threadIdx.x;
    int dl = t & 7, pslot = t >> 3;
    __shared__ float sa[512*8], sb[512*8];
    __shared__ float sstat[8*4];
    if (t < 32) sstat[t] = g_stats[(rg*DIM + dblk*8)*4 + t];
    __syncthreads();
    for (int idx=t; idx<512*8; idx+=256){
        int n = idx>>3, dd = idx&7;
        float v  = cur[((size_t)(g*NGR+n))*DIM + dblk*8 + dd];
        float xc = v - sstat[dd*4+3];
        float cc = sstat[dd*4+2];
        sa[idx] = cc*xc*xc;
        sb[idx] = -2.f*cc*xc;
    }
    __syncthreads();
    float mnc = sstat[dl*4+0], step = sstat[dl*4+1], c2 = sstat[dl*4+2];
    float gp[4], P0[4], acc[4];
    #pragma unroll
    for (int j=0;j<4;j++){
        int p = pblk*128 + pslot + 32*j;
        gp[j]  = fmaf((float)p, step, mnc);
        P0[j]  = c2*gp[j]*gp[j];
        acc[j] = 0.f;
    }
    #pragma unroll 4
    for (int n=0;n<512;n++){
        float a = sa[n*8+dl], bb = sb[n*8+dl];
        #pragma unroll
        for (int j=0;j<4;j++)
            acc[j] += ex2(fmaf(bb, gp[j], P0[j]) + a);
    }
    int dG = dblk*8 + dl;
    #pragma unroll
    for (int j=0;j<4;j++){
        int p = pblk*128 + pslot + 32*j;
        if (p < GRID_PTS) g_dens[((size_t)(rg*DIM + dG))*512 + p] = acc[j];
    }
}

// ---------------- cdf + soft quantiles: one warp per (rg,d) ----------------
__global__ void k_quant(){
    int t = threadIdx.x; int wrp = t>>5, lane = t&31;
    int ww = blockIdx.x*4 + wrp;          // 0..1535
    int rg = ww >> 7, d = ww & 127;
    const float* dn = &g_dens[((size_t)(rg*DIM + d))*512];
    float cdfl[16];
    float run = 0.f;
    #pragma unroll
    for (int i=0;i<16;i++){
        int p = lane*16 + i;
        float v = (p < GRID_PTS) ? dn[p] : 0.f;
        run += v; cdfl[i] = run;
    }
    float tot = run, xs = run;
    for (int o=1;o<32;o<<=1){ float v=__shfl_up_sync(0xffffffffu,xs,o); if (lane>=o) xs+=v; }
    float basev = xs - tot;
    #pragma unroll
    for (int i=0;i<16;i++) cdfl[i] += basev;
    float total = __shfl_sync(0xffffffffu, cdfl[15], 31);
    float invT  = 1.f/fmaxf(total, 1e-8f);
    const float* st = &g_stats[(rg*DIM + d)*4];
    float gv0 = st[0] + st[3];   // un-centered grid origin (mn - 1e-6)
    float step = st[1];
    for (int q=0;q<NQ;q++){
        float qq = q*(1.f/19.f);
        float sw=0.f, swg=0.f;
        #pragma unroll
        for (int i=0;i<16;i++){
            int p = lane*16 + i;
            if (p < GRID_PTS){
                float dist = fabsf(fmaf(cdfl[i], invT, -qq));
                float w = __fdividef(1.f, 1.f + __expf(100.f*dist));
                sw += w;
                swg = fmaf(w, fmaf((float)p, step, gv0), swg);
            }
        }
        for (int o=16;o;o>>=1){ sw  += __shfl_xor_sync(0xffffffffu,sw,o);
                                swg += __shfl_xor_sync(0xffffffffu,swg,o); }
        if (lane==0) g_kf[rg*2560 + d*NQ + q] = swg/(sw + 1e-8f);
    }
}

// ---------------- per-readout projections, accumulate (h+kde)/3 ----------------
__global__ void k_proj(const float* lpW0,const float* lpb0,const float* lpW1,const float* lpb1,
                       const float* lpW2,const float* lpb2,
                       const float* kW0,const float* kb0,const float* kW1,const float* kb1,
                       const float* kW2,const float* kb2){
    int rg = blockIdx.x; int g = rg&3; int ro = rg>>2;
    const float* lpW = (ro==0)?lpW0:(ro==1)?lpW1:lpW2;
    const float* lpb = (ro==0)?lpb0:(ro==1)?lpb1:lpb2;
    const float* kW  = (ro==0)?kW0 :(ro==1)?kW1 :kW2;
    const float* kb  = (ro==0)?kb0 :(ro==1)?kb1 :kb2;
    int t = threadIdx.x; int o = t&31, seg = t>>5;
    const float* kf = &g_kf[rg*2560];
    float kp = 0.f;
    for (int i=seg*320; i<seg*320+320; i++)
        kp = fmaf(kf[i], kW[i*32 + o], kp);
    const float* wp = &g_pool[rg*DIM];
    float hp = 0.f;
    for (int d=seg*16; d<seg*16+16; d++)
        hp = fmaf(wp[d], lpW[d*32 + o], hp);
    __shared__ float r1[256], r2[256];
    r1[t]=kp; r2[t]=hp; __syncthreads();
    if (t < 32){
        float ks=0.f, hs=0.f;
        for (int s=0;s<8;s++){ ks += r1[t + s*32]; hs += r2[t + s*32]; }
        float val = (ks + kb[t]) + (hs + lpb[t]);
        atomicAdd(&g_acc[g*32 + t], val*(1.f/3.f));
    }
}

__global__ void k_final(const float* __restrict__ beta, const float* __restrict__ h0,
                        float* __restrict__ out){
    int t = threadIdx.x; int g = t>>5, o = t&31;
    float v = g_acc[g*32 + o]*beta[o];
    for (int ofs=16; ofs; ofs>>=1) v += __shfl_xor_sync(0xffffffffu, v, ofs);
    if (o==0) out[g] = v + h0[0];
}

// ---------------- launch ----------------
extern "C" void kernel_launch(void* const* d_in, const int* in_sizes, int n_in,
                              void* d_out, int out_size){
    const float* x   = (const float*)d_in[0];
    const int*   ei  = (const int*)d_in[1];       // int32! (JAX x64 disabled)
    const float* W0  = (const float*)d_in[3];
    const float* as0 = (const float*)d_in[4];
    const float* ad0 = (const float*)d_in[5];
    const float* b0  = (const float*)d_in[6];
    const float* W1  = (const float*)d_in[7];
    const float* as1 = (const float*)d_in[8];
    const float* ad1 = (const float*)d_in[9];
    const float* b1  = (const float*)d_in[10];
    const float* lpW0=(const float*)d_in[11]; const float* lpb0=(const float*)d_in[12];
    const float* lpW1=(const float*)d_in[13]; const float* lpb1=(const float*)d_in[14];
    const float* lpW2=(const float*)d_in[15]; const float* lpb2=(const float*)d_in[16];
    const float* kW0 =(const float*)d_in[17]; const float* kb0 =(const float*)d_in[18];
    const float* kW1 =(const float*)d_in[19]; const float* kb1 =(const float*)d_in[20];
    const float* kW2 =(const float*)d_in[21]; const float* kb2 =(const float*)d_in[22];
    const float* poolw=(const float*)d_in[23];
    const float* beta =(const float*)d_in[24];
    const float* h0   =(const float*)d_in[25];
    float* out = (float*)d_out;

    k_zero <<<8, 256>>>();
    k_count<<<128, 256>>>(ei);
    k_scan <<<1, 32>>>();
    k_fill <<<128, 256>>>(ei);

    k_lin<<<N_NODES, 128>>>(x, 0, W0, as0, ad0);
    k_att<<<N_NODES, 128>>>(b0, 0);            // -> g_cur1 (with ReLU)
    k_lin<<<N_NODES, 128>>>(x, 1, W1, as1, ad1);
    k_att<<<N_NODES, 128>>>(b1, 1);            // -> g_cur2

    k_stats<<<NRG, 512>>>(x, poolw);
    k_dens <<<768, 256>>>(x);
    k_quant<<<384, 128>>>();
    k_proj <<<NRG, 256>>>(lpW0,lpb0,lpW1,lpb1,lpW2,lpb2,kW0,kb0,kW1,kb1,kW2,kb2);
    k_final<<<1, 128>>>(beta, h0, out);
}

// round 3
// speedup vs baseline: 1.2615x; 1.2615x over previous
#include <cuda_runtime.h>

#define N_NODES 2048
#define NGR 512
#define NGRAPH 4
#define NEDGE 32768
#define DIM 128
#define HEADS 4
#define GRID_PTS 500
#define NQ 20
#define NRG 12   // 3 readouts x 4 graphs
#define DEGCAP 64

typedef unsigned long long ull;

// ---------------- device scratch ----------------
__device__ float g_xh[N_NODES*DIM];
__device__ float g_als[N_NODES*HEADS];
__device__ float g_ald[N_NODES*HEADS];
__device__ float g_cur1[N_NODES*DIM];
__device__ float g_cur2[N_NODES*DIM];
__device__ float g_xT [DIM*N_NODES];
__device__ float g_c1T[DIM*N_NODES];
__device__ float g_c2T[DIM*N_NODES];
__device__ int   g_cursor[N_NODES];
__device__ int   g_adjB[N_NODES*DEGCAP];
__device__ float g_stats[NRG*DIM*4];   // {mn_centered, step, c2, mid}
__device__ float g_pool[NRG*DIM];
__device__ float g_dens[NRG*DIM*512];
__device__ float g_kf[NRG*DIM*NQ];
__device__ float g_acc[NGRAPH*32];

__device__ __forceinline__ float ex2(float x){
    float y; asm("ex2.approx.ftz.f32 %0, %1;" : "=f"(y) : "f"(x)); return y;
}
__device__ __forceinline__ ull pk2(float lo, float hi){
    ull o; asm("mov.b64 %0, {%1, %2};" : "=l"(o) : "f"(lo), "f"(hi)); return o;
}
__device__ __forceinline__ void up2(float& lo, float& hi, ull v){
    asm("mov.b64 {%0, %1}, %2;" : "=f"(lo), "=f"(hi) : "l"(v));
}
__device__ __forceinline__ ull mul2(ull a, ull b){
    ull o; asm("mul.rn.f32x2 %0, %1, %2;" : "=l"(o) : "l"(a), "l"(b)); return o;
}
__device__ __forceinline__ ull add2(ull a, ull b){
    ull o; asm("add.rn.f32x2 %0, %1, %2;" : "=l"(o) : "l"(a), "l"(b)); return o;
}

// ---------------- prep: zero counters + transpose x ----------------
__global__ void k_prep(const float* __restrict__ x){
    __shared__ float tile[32][129];
    int b = blockIdx.x, t = threadIdx.x;
    int n0 = b*32;
    int gt = b*256 + t;
    if (gt < N_NODES) g_cursor[gt] = 0;
    if (gt < NGRAPH*32) g_acc[gt] = 0.f;
    #pragma unroll
    for (int i=0;i<16;i++){
        int idx = t + i*256;
        int nn = idx>>7, d = idx&127;
        tile[nn][d] = x[(size_t)(n0+nn)*DIM + d];
    }
    __syncthreads();
    #pragma unroll
    for (int i=0;i<16;i++){
        int idx = t + i*256;
        int d = idx>>5, nn = idx&31;
        g_xT[(size_t)d*N_NODES + n0 + nn] = tile[nn][d];
    }
}

// ---------------- bucketed adjacency ----------------
__global__ void k_fill(const int* __restrict__ ei){
    int e = blockIdx.x*blockDim.x + threadIdx.x;
    if (e < NEDGE){
        int d = ei[NEDGE+e];
        int pos = atomicAdd(&g_cursor[d],1);
        if (pos < DEGCAP) g_adjB[d*DEGCAP + pos] = ei[e];
    }
}

// ---------------- GAT linear: 8 nodes per block ----------------
__global__ void k_lin(const float* __restrict__ x, int layer,
                      const float* __restrict__ W,
                      const float* __restrict__ as_,
                      const float* __restrict__ ad_){
    const float* cur = layer ? g_cur1 : x;
    int b = blockIdx.x, t = threadIdx.x;
    int n0 = b*8;
    __shared__ float srow[8][128];
    #pragma unroll
    for (int i=0;i<8;i++){
        int idx = t + i*128;
        srow[idx>>7][idx&127] = cur[(size_t)n0*DIM + idx];
    }
    __syncthreads();
    float acc[8] = {0,0,0,0,0,0,0,0};
    #pragma unroll 4
    for (int k4=0;k4<32;k4++){
        float w0 = W[(k4*4+0)*DIM + t];
        float w1 = W[(k4*4+1)*DIM + t];
        float w2 = W[(k4*4+2)*DIM + t];
        float w3 = W[(k4*4+3)*DIM + t];
        #pragma unroll
        for (int j=0;j<8;j++){
            float4 sv = *(const float4*)&srow[j][k4*4];
            acc[j] = fmaf(sv.x, w0, acc[j]);
            acc[j] = fmaf(sv.y, w1, acc[j]);
            acc[j] = fmaf(sv.z, w2, acc[j]);
            acc[j] = fmaf(sv.w, w3, acc[j]);
        }
    }
    int hw = t>>5;
    float a_s = as_[t], a_d = ad_[t];
    #pragma unroll
    for (int j=0;j<8;j++){
        g_xh[(size_t)(n0+j)*DIM + t] = acc[j];
        float ps = acc[j]*a_s, pd = acc[j]*a_d;
        for (int o=16;o;o>>=1){
            ps += __shfl_xor_sync(0xffffffffu, ps, o);
            pd += __shfl_xor_sync(0xffffffffu, pd, o);
        }
        if ((t&31)==0){
            g_als[(n0+j)*HEADS + hw] = ps;
            g_ald[(n0+j)*HEADS + hw] = pd;
        }
    }
}

// ---------------- GAT attention + aggregation (gather per node) ----------------
__global__ void k_att(const float* __restrict__ bias, int layer){
    float* out  = layer ? g_cur2 : g_cur1;
    float* outT = layer ? g_c2T  : g_c1T;
    int relu = (layer==0);
    int n = blockIdx.x, t = threadIdx.x;
    int w = t>>5, lane = t&31;
    int deg = g_cursor[n]; if (deg > DEGCAP) deg = DEGCAP;
    const int* adj = &g_adjB[n*DEGCAP];
    __shared__ float smax[HEADS], sinv[HEADS];
    float aldn = g_ald[n*HEADS + w];
    float m = -1e30f;
    for (int i=lane;i<deg+1;i+=32){
        int s = (i<deg) ? adj[i] : n;
        float z = g_als[s*HEADS+w] + aldn;
        z = (z>0.f) ? z : 0.2f*z;
        m = fmaxf(m, z);
    }
    for (int o=16;o;o>>=1) m = fmaxf(m, __shfl_xor_sync(0xffffffffu,m,o));
    float sum = 0.f;
    for (int i=lane;i<deg+1;i+=32){
        int s = (i<deg) ? adj[i] : n;
        float z = g_als[s*HEADS+w] + aldn;
        z = (z>0.f) ? z : 0.2f*z;
        sum += __expf(z - m);
    }
    for (int o=16;o;o>>=1) sum += __shfl_xor_sync(0xffffffffu,sum,o);
    if (lane==0){ smax[w]=m; sinv[w]=1.f/(sum + 1e-16f); }
    __syncthreads();
    float m2 = smax[w], inv = sinv[w];
    float acc = 0.f;
    for (int i=0;i<deg+1;i++){
        int s = (i<deg) ? adj[i] : n;
        float z = g_als[s*HEADS+w] + aldn;
        z = (z>0.f) ? z : 0.2f*z;
        float alpha = __expf(z - m2)*inv;
        acc = fmaf(alpha, g_xh[(size_t)s*DIM + t], acc);
    }
    acc += bias[t];
    if (relu) acc = fmaxf(acc, 0.f);
    out[(size_t)n*DIM + t] = acc;
    outT[(size_t)t*N_NODES + n] = acc;
}

// ---------------- fused stats + KDE density ----------------
// 768 blocks = 12 rg x 64 dblk (2 dims each). Block 64 threads: warp w = dim dblk*2+w.
// Thread: 16 consecutive grid points, two 8-long geometric chains packed f32x2.
__global__ void __launch_bounds__(64,16) k_dens(const float* __restrict__ pw){
    int b = blockIdx.x;
    int rg = b >> 6, dblk = b & 63;
    int g = rg & 3, ro = rg >> 2;
    const float* baseT = (ro==0) ? g_xT : (ro==1) ? g_c1T : g_c2T;
    int t = threadIdx.x, w = t>>5, lane = t&31;
    int d = dblk*2 + w;
    const float* row = baseT + (size_t)d*N_NODES + g*NGR;

    // stats over 512 values (16 per lane, coalesced)
    float v[16];
    float mn=1e30f, mx=-1e30f, s1=0.f, s2=0.f;
    #pragma unroll
    for (int i=0;i<16;i++){
        float x = row[i*32 + lane];
        v[i] = x;
        mn = fminf(mn,x); mx = fmaxf(mx,x);
        s1 += x; s2 = fmaf(x,x,s2);
    }
    #pragma unroll
    for (int o=16;o;o>>=1){
        mn = fminf(mn, __shfl_xor_sync(0xffffffffu,mn,o));
        mx = fmaxf(mx, __shfl_xor_sync(0xffffffffu,mx,o));
        s1 += __shfl_xor_sync(0xffffffffu,s1,o);
        s2 += __shfl_xor_sync(0xffffffffu,s2,o);
    }
    float mean = s1*(1.f/512.f);
    float var  = fmaxf(s2*(1.f/512.f) - mean*mean, 0.f);
    float stdv = sqrtf(var) + 3.3333333e-9f;
    float h    = 0.30440506f*stdv;                   // 1.06*512^-0.2
    float c2   = -0.72134752f/(h*h);                 // -0.5*log2(e)/h^2
    float mnA = mn - 1e-6f, mxA = mx + 1e-6f;
    float step = (mxA - mnA)*(1.f/499.f);
    float mid  = 0.5f*(mnA + mxA);
    if (lane==0){
        float* st = &g_stats[(rg*DIM + d)*4];
        st[0] = mnA - mid; st[1] = step; st[2] = c2; st[3] = mid;
        g_pool[rg*DIM + d] = pw[0]*mean + pw[1]*mx;
    }
    // per-node (a,b) in log2 space
    __shared__ float2 sab[2][520];
    #pragma unroll
    for (int i=0;i<16;i++){
        float xc = v[i] - mid;
        sab[w][i*32 + lane] = make_float2(c2*xc*xc, -2.f*c2*xc);
    }
    __syncthreads();

    // main loop: slot = lane, 16 points [slot*16, slot*16+16)
    int slot = lane;
    float mnc = mnA - mid;
    float g0  = fmaf((float)(slot*16), step, mnc);
    float q0  = c2*g0*g0;
    float K1  = 2.f*c2*step, K2 = c2*step*step;
    float hR  = fmaf(K1, g0, K2);
    float t1  = ex2(2.f*K2);
    float t2  = t1*t1;
    float sc  = t2*t2;
    ull s2p   = pk2(sc, sc);
    ull acc2[8];
    #pragma unroll
    for (int k=0;k<8;k++) acc2[k] = 0ull;
    const float2* abp = sab[w];
    for (int n=0;n<512;n++){
        float2 abv = abp[n];
        float QA  = fmaf(abv.y, g0, q0) + abv.x;   // log2 density arg at point 0
        float Ra  = fmaf(abv.y, step, hR);         // log2 one-step ratio
        float eA  = ex2(QA);
        float rho = ex2(Ra);
        float eB  = eA*rho;
        float rA  = rho*rho*t1;
        float rB  = rA*t2;
        ull e2 = pk2(eA, eB);
        ull r2 = pk2(rA, rB);
        acc2[0] = add2(acc2[0], e2);
        #pragma unroll
        for (int k=1;k<8;k++){
            e2 = mul2(e2, r2);
            r2 = mul2(r2, s2p);
            acc2[k] = add2(acc2[k], e2);
        }
    }
    float* dout = &g_dens[((size_t)(rg*DIM + d))*512 + slot*16];
    #pragma unroll
    for (int k=0;k<8;k++){
        float lo, hi; up2(lo, hi, acc2[k]);
        dout[2*k] = lo; dout[2*k+1] = hi;
    }
}

// ---------------- cdf + soft quantiles: one warp per (rg,d) ----------------
__global__ void k_quant(){
    int t = threadIdx.x; int wrp = t>>5, lane = t&31;
    int ww = blockIdx.x*4 + wrp;          // 0..1535
    int rg = ww >> 7, d = ww & 127;
    const float* dn = &g_dens[((size_t)(rg*DIM + d))*512];
    float cdfl[16];
    float run = 0.f;
    #pragma unroll
    for (int i=0;i<16;i++){
        int p = lane*16 + i;
        float vv = (p < GRID_PTS) ? dn[p] : 0.f;
        run += vv; cdfl[i] = run;
    }
    float tot = run, xs = run;
    for (int o=1;o<32;o<<=1){ float vv=__shfl_up_sync(0xffffffffu,xs,o); if (lane>=o) xs+=vv; }
    float basev = xs - tot;
    #pragma unroll
    for (int i=0;i<16;i++) cdfl[i] += basev;
    float total = __shfl_sync(0xffffffffu, cdfl[15], 31);
    float invT  = 1.f/fmaxf(total, 1e-8f);
    const float* st = &g_stats[(rg*DIM + d)*4];
    float gv0 = st[0] + st[3];
    float step = st[1];
    for (int q=0;q<NQ;q++){
        float qq = q*(1.f/19.f);
        float sw=0.f, swg=0.f;
        #pragma unroll
        for (int i=0;i<16;i++){
            int p = lane*16 + i;
            if (p < GRID_PTS){
                float dist = fabsf(fmaf(cdfl[i], invT, -qq));
                float wgt = __fdividef(1.f, 1.f + __expf(100.f*dist));
                sw += wgt;
                swg = fmaf(wgt, fmaf((float)p, step, gv0), swg);
            }
        }
        for (int o=16;o;o>>=1){ sw  += __shfl_xor_sync(0xffffffffu,sw,o);
                                swg += __shfl_xor_sync(0xffffffffu,swg,o); }
        if (lane==0) g_kf[rg*2560 + d*NQ + q] = swg/(sw + 1e-8f);
    }
}

// ---------------- per-readout projections ----------------
__global__ void k_proj(const float* lpW0,const float* lpb0,const float* lpW1,const float* lpb1,
                       const float* lpW2,const float* lpb2,
                       const float* kW0,const float* kb0,const float* kW1,const float* kb1,
                       const float* kW2,const float* kb2){
    int rg = blockIdx.x; int g = rg&3; int ro = rg>>2;
    const float* lpW = (ro==0)?lpW0:(ro==1)?lpW1:lpW2;
    const float* lpb = (ro==0)?lpb0:(ro==1)?lpb1:lpb2;
    const float* kW  = (ro==0)?kW0 :(ro==1)?kW1 :kW2;
    const float* kb  = (ro==0)?kb0 :(ro==1)?kb1 :kb2;
    int t = threadIdx.x; int o = t&31, seg = t>>5;
    const float* kf = &g_kf[rg*2560];
    float kp = 0.f;
    for (int i=seg*320; i<seg*320+320; i++)
        kp = fmaf(kf[i], kW[i*32 + o], kp);
    const float* wp = &g_pool[rg*DIM];
    float hp = 0.f;
    for (int d=seg*16; d<seg*16+16; d++)
        hp = fmaf(wp[d], lpW[d*32 + o], hp);
    __shared__ float r1[256], r2s[256];
    r1[t]=kp; r2s[t]=hp; __syncthreads();
    if (t < 32){
        float ks=0.f, hs=0.f;
        for (int s=0;s<8;s++){ ks += r1[t + s*32]; hs += r2s[t + s*32]; }
        float val = (ks + kb[t]) + (hs + lpb[t]);
        atomicAdd(&g_acc[g*32 + t], val*(1.f/3.f));
    }
}

__global__ void k_final(const float* __restrict__ beta, const float* __restrict__ h0,
                        float* __restrict__ out){
    int t = threadIdx.x; int g = t>>5, o = t&31;
    float v = g_acc[g*32 + o]*beta[o];
    for (int ofs=16; ofs; ofs>>=1) v += __shfl_xor_sync(0xffffffffu, v, ofs);
    if (o==0) out[g] = v + h0[0];
}

// ---------------- launch ----------------
extern "C" void kernel_launch(void* const* d_in, const int* in_sizes, int n_in,
                              void* d_out, int out_size){
    const float* x   = (const float*)d_in[0];
    const int*   ei  = (const int*)d_in[1];
    const float* W0  = (const float*)d_in[3];
    const float* as0 = (const float*)d_in[4];
    const float* ad0 = (const float*)d_in[5];
    const float* b0  = (const float*)d_in[6];
    const float* W1  = (const float*)d_in[7];
    const float* as1 = (const float*)d_in[8];
    const float* ad1 = (const float*)d_in[9];
    const float* b1  = (const float*)d_in[10];
    const float* lpW0=(const float*)d_in[11]; const float* lpb0=(const float*)d_in[12];
    const float* lpW1=(const float*)d_in[13]; const float* lpb1=(const float*)d_in[14];
    const float* lpW2=(const float*)d_in[15]; const float* lpb2=(const float*)d_in[16];
    const float* kW0 =(const float*)d_in[17]; const float* kb0 =(const float*)d_in[18];
    const float* kW1 =(const float*)d_in[19]; const float* kb1 =(const float*)d_in[20];
    const float* kW2 =(const float*)d_in[21]; const float* kb2 =(const float*)d_in[22];
    const float* poolw=(const float*)d_in[23];
    const float* beta =(const float*)d_in[24];
    const float* h0   =(const float*)d_in[25];
    float* out = (float*)d_out;

    k_prep<<<64, 256>>>(x);
    k_fill<<<128, 256>>>(ei);

    k_lin<<<256, 128>>>(x, 0, W0, as0, ad0);
    k_att<<<N_NODES, 128>>>(b0, 0);            // -> g_cur1 (+ReLU) and g_c1T
    k_lin<<<256, 128>>>(x, 1, W1, as1, ad1);
    k_att<<<N_NODES, 128>>>(b1, 1);            // -> g_cur2 and g_c2T

    k_dens <<<768, 64>>>(poolw);               // fused stats + density
    k_quant<<<384, 128>>>();
    k_proj <<<NRG, 256>>>(lpW0,lpb0,lpW1,lpb1,lpW2,lpb2,kW0,kb0,kW1,kb1,kW2,kb2);
    k_final<<<1, 128>>>(beta, h0, out);
}

// round 4
// speedup vs baseline: 1.2967x; 1.0280x over previous
#include <cuda_runtime.h>

#define N_NODES 2048
#define NGR 512
#define NGRAPH 4
#define NEDGE 32768
#define DIM 128
#define HEADS 4
#define GRID_PTS 500
#define NQ 20
#define NRG 12
#define DEGCAP 64

typedef unsigned long long ull;

// ---------------- device scratch ----------------
__device__ float g_xh[N_NODES*DIM];
__device__ float g_als[N_NODES*HEADS];
__device__ float g_ald[N_NODES*HEADS];
__device__ float g_cur1[N_NODES*DIM];
__device__ float g_cur2[N_NODES*DIM];
__device__ float g_xT [DIM*N_NODES];
__device__ float g_c1T[DIM*N_NODES];
__device__ float g_c2T[DIM*N_NODES];
__device__ int   g_cursor[N_NODES];
__device__ int   g_adjB[N_NODES*DEGCAP];
__device__ float g_pool[NRG*DIM];
__device__ float g_kf[NRG*DIM*NQ];
__device__ float g_acc[NGRAPH*32];
__device__ int   g_done;

__device__ __forceinline__ float ex2(float x){
    float y; asm("ex2.approx.ftz.f32 %0, %1;" : "=f"(y) : "f"(x)); return y;
}
__device__ __forceinline__ ull pk2(float lo, float hi){
    ull o; asm("mov.b64 %0, {%1, %2};" : "=l"(o) : "f"(lo), "f"(hi)); return o;
}
__device__ __forceinline__ void up2(float& lo, float& hi, ull v){
    asm("mov.b64 {%0, %1}, %2;" : "=f"(lo), "=f"(hi) : "l"(v));
}
__device__ __forceinline__ ull mul2(ull a, ull b){
    ull o; asm("mul.rn.f32x2 %0, %1, %2;" : "=l"(o) : "l"(a), "l"(b)); return o;
}
__device__ __forceinline__ ull add2(ull a, ull b){
    ull o; asm("add.rn.f32x2 %0, %1, %2;" : "=l"(o) : "l"(a), "l"(b)); return o;
}

// ---------------- prep: zero counters + transpose x ----------------
__global__ void k_prep(const float* __restrict__ x){
    __shared__ float tile[32][129];
    int b = blockIdx.x, t = threadIdx.x;
    int n0 = b*32;
    int gt = b*256 + t;
    if (gt < N_NODES) g_cursor[gt] = 0;
    if (gt < NGRAPH*32) g_acc[gt] = 0.f;
    if (gt == 0) g_done = 0;
    #pragma unroll
    for (int i=0;i<16;i++){
        int idx = t + i*256;
        int nn = idx>>7, d = idx&127;
        tile[nn][d] = x[(size_t)(n0+nn)*DIM + d];
    }
    __syncthreads();
    #pragma unroll
    for (int i=0;i<16;i++){
        int idx = t + i*256;
        int d = idx>>5, nn = idx&31;
        g_xT[(size_t)d*N_NODES + n0 + nn] = tile[nn][d];
    }
}

// ---------------- bucketed adjacency ----------------
__global__ void k_fill(const int* __restrict__ ei){
    int e = blockIdx.x*blockDim.x + threadIdx.x;
    if (e < NEDGE){
        int d = ei[NEDGE+e];
        int pos = atomicAdd(&g_cursor[d],1);
        if (pos < DEGCAP) g_adjB[d*DEGCAP + pos] = ei[e];
    }
}

// ---------------- GAT linear: 8 nodes per block ----------------
__global__ void k_lin(const float* __restrict__ x, int layer,
                      const float* __restrict__ W,
                      const float* __restrict__ as_,
                      const float* __restrict__ ad_){
    const float* cur = layer ? g_cur1 : x;
    int b = blockIdx.x, t = threadIdx.x;
    int n0 = b*8;
    __shared__ float srow[8][128];
    #pragma unroll
    for (int i=0;i<8;i++){
        int idx = t + i*128;
        srow[idx>>7][idx&127] = cur[(size_t)n0*DIM + idx];
    }
    __syncthreads();
    float acc[8] = {0,0,0,0,0,0,0,0};
    #pragma unroll 4
    for (int k4=0;k4<32;k4++){
        float w0 = W[(k4*4+0)*DIM + t];
        float w1 = W[(k4*4+1)*DIM + t];
        float w2 = W[(k4*4+2)*DIM + t];
        float w3 = W[(k4*4+3)*DIM + t];
        #pragma unroll
        for (int j=0;j<8;j++){
            float4 sv = *(const float4*)&srow[j][k4*4];
            acc[j] = fmaf(sv.x, w0, acc[j]);
            acc[j] = fmaf(sv.y, w1, acc[j]);
            acc[j] = fmaf(sv.z, w2, acc[j]);
            acc[j] = fmaf(sv.w, w3, acc[j]);
        }
    }
    int hw = t>>5;
    float a_s = as_[t], a_d = ad_[t];
    #pragma unroll
    for (int j=0;j<8;j++){
        g_xh[(size_t)(n0+j)*DIM + t] = acc[j];
        float ps = acc[j]*a_s, pd = acc[j]*a_d;
        for (int o=16;o;o>>=1){
            ps += __shfl_xor_sync(0xffffffffu, ps, o);
            pd += __shfl_xor_sync(0xffffffffu, pd, o);
        }
        if ((t&31)==0){
            g_als[(n0+j)*HEADS + hw] = ps;
            g_ald[(n0+j)*HEADS + hw] = pd;
        }
    }
}

// ---------------- GAT attention + aggregation ----------------
__global__ void k_att(const float* __restrict__ bias, int layer){
    float* out  = layer ? g_cur2 : g_cur1;
    float* outT = layer ? g_c2T  : g_c1T;
    int relu = (layer==0);
    int n = blockIdx.x, t = threadIdx.x;
    int w = t>>5, lane = t&31;
    int deg = g_cursor[n]; if (deg > DEGCAP) deg = DEGCAP;
    int cnt = deg + 1;
    __shared__ int   sadj[DEGCAP+1];
    __shared__ float sal[HEADS][DEGCAP+1];
    if (t < cnt) sadj[t] = (t < deg) ? g_adjB[n*DEGCAP + t] : n;
    __syncthreads();
    float aldn = g_ald[n*HEADS + w];
    int i0 = lane, i1 = lane+32, i2 = lane+64;
    float z0=-1e30f, z1=-1e30f, z2=-1e30f;
    if (i0 < cnt){ float z = g_als[sadj[i0]*HEADS+w] + aldn; z0 = (z>0.f)?z:0.2f*z; }
    if (i1 < cnt){ float z = g_als[sadj[i1]*HEADS+w] + aldn; z1 = (z>0.f)?z:0.2f*z; }
    if (i2 < cnt){ float z = g_als[sadj[i2]*HEADS+w] + aldn; z2 = (z>0.f)?z:0.2f*z; }
    float m = fmaxf(z0, fmaxf(z1, z2));
    #pragma unroll
    for (int o=16;o;o>>=1) m = fmaxf(m, __shfl_xor_sync(0xffffffffu,m,o));
    float e0 = (i0<cnt) ? __expf(z0-m) : 0.f;
    float e1 = (i1<cnt) ? __expf(z1-m) : 0.f;
    float e2 = (i2<cnt) ? __expf(z2-m) : 0.f;
    if (i0<cnt) sal[w][i0] = e0;
    if (i1<cnt) sal[w][i1] = e1;
    if (i2<cnt) sal[w][i2] = e2;
    float sum = e0 + e1 + e2;
    #pragma unroll
    for (int o=16;o;o>>=1) sum += __shfl_xor_sync(0xffffffffu,sum,o);
    float inv = 1.f/(sum + 1e-16f);
    __syncthreads();
    float acc = 0.f;
    int i = 0;
    for (; i+4 <= cnt; i += 4){
        int s0=sadj[i], s1=sadj[i+1], s2=sadj[i+2], s3=sadj[i+3];
        float a0=sal[w][i], a1=sal[w][i+1], a2=sal[w][i+2], a3=sal[w][i+3];
        float x0=g_xh[(size_t)s0*DIM+t], x1=g_xh[(size_t)s1*DIM+t];
        float x2=g_xh[(size_t)s2*DIM+t], x3=g_xh[(size_t)s3*DIM+t];
        acc = fmaf(a0,x0,acc); acc = fmaf(a1,x1,acc);
        acc = fmaf(a2,x2,acc); acc = fmaf(a3,x3,acc);
    }
    for (; i < cnt; i++)
        acc = fmaf(sal[w][i], g_xh[(size_t)sadj[i]*DIM+t], acc);
    acc = fmaf(acc, inv, bias[t]);
    if (relu) acc = fmaxf(acc, 0.f);
    out [(size_t)n*DIM + t] = acc;
    outT[(size_t)t*N_NODES + n] = acc;
}

// ---------------- fused stats + KDE density + cdf + soft quantiles ----------------
// 1536 blocks = 12 rg x 128 d, one warp each. Lane: 16 consecutive grid points
// (two 8-long geometric chains packed f32x2), then in-register cdf + quantiles.
__global__ void __launch_bounds__(32,16) k_densq(const float* __restrict__ pw){
    int b = blockIdx.x;
    int rg = b >> 7, d = b & 127;
    int g = rg & 3, ro = rg >> 2;
    const float* baseT = (ro==0) ? g_xT : (ro==1) ? g_c1T : g_c2T;
    int lane = threadIdx.x;
    const float* row = baseT + (size_t)d*N_NODES + g*NGR;

    // stats over 512 values
    float v[16];
    float mn=1e30f, mx=-1e30f, s1=0.f, s2=0.f;
    #pragma unroll
    for (int i=0;i<16;i++){
        float x = row[i*32 + lane];
        v[i] = x;
        mn = fminf(mn,x); mx = fmaxf(mx,x);
        s1 += x; s2 = fmaf(x,x,s2);
    }
    #pragma unroll
    for (int o=16;o;o>>=1){
        mn = fminf(mn, __shfl_xor_sync(0xffffffffu,mn,o));
        mx = fmaxf(mx, __shfl_xor_sync(0xffffffffu,mx,o));
        s1 += __shfl_xor_sync(0xffffffffu,s1,o);
        s2 += __shfl_xor_sync(0xffffffffu,s2,o);
    }
    float mean = s1*(1.f/512.f);
    float var  = fmaxf(s2*(1.f/512.f) - mean*mean, 0.f);
    float stdv = sqrtf(var) + 3.3333333e-9f;
    float h    = 0.30440506f*stdv;                   // 1.06*512^-0.2
    float c2   = -0.72134752f/(h*h);                 // -0.5*log2(e)/h^2
    float mnA = mn - 1e-6f, mxA = mx + 1e-6f;
    float step = (mxA - mnA)*(1.f/499.f);
    float mid  = 0.5f*(mnA + mxA);
    if (lane==0) g_pool[rg*DIM + d] = pw[0]*mean + pw[1]*mx;

    __shared__ float2 sab[512];
    #pragma unroll
    for (int i=0;i<16;i++){
        float xc = v[i] - mid;
        sab[i*32 + lane] = make_float2(c2*xc*xc, -2.f*c2*xc);
    }
    __syncwarp();

    // density chains: lane -> points [lane*16, lane*16+16)
    float mnc = mnA - mid;
    float g0  = fmaf((float)(lane*16), step, mnc);
    float q0  = c2*g0*g0;
    float K1  = 2.f*c2*step, K2 = c2*step*step;
    float hR  = fmaf(K1, g0, K2);
    float t1  = ex2(2.f*K2);
    float t2  = t1*t1;
    float sc  = t2*t2;
    ull s2p   = pk2(sc, sc);
    ull acc2[8];
    #pragma unroll
    for (int k=0;k<8;k++) acc2[k] = 0ull;
    for (int n=0;n<512;n++){
        float2 abv = sab[n];
        float QA  = fmaf(abv.y, g0, q0) + abv.x;
        float Ra  = fmaf(abv.y, step, hR);
        float eA  = ex2(QA);
        float rho = ex2(Ra);
        float eB  = eA*rho;
        float rA  = rho*rho*t1;
        float rB  = rA*t2;
        ull e2 = pk2(eA, eB);
        ull r2 = pk2(rA, rB);
        acc2[0] = add2(acc2[0], e2);
        #pragma unroll
        for (int k=1;k<8;k++){
            e2 = mul2(e2, r2);
            r2 = mul2(r2, s2p);
            acc2[k] = add2(acc2[k], e2);
        }
    }
    // unpack + mask p>=500
    float dens[16];
    #pragma unroll
    for (int k=0;k<8;k++) up2(dens[2*k], dens[2*k+1], acc2[k]);
    int pbase = lane*16;
    #pragma unroll
    for (int j=0;j<16;j++) if (pbase + j >= GRID_PTS) dens[j] = 0.f;
    // cdf: in-lane running sum + warp exclusive scan
    float cdfl[16];
    float run = 0.f;
    #pragma unroll
    for (int j=0;j<16;j++){ run += dens[j]; cdfl[j] = run; }
    float tot = run, xs = run;
    for (int o=1;o<32;o<<=1){ float t_=__shfl_up_sync(0xffffffffu,xs,o); if (lane>=o) xs+=t_; }
    float basev = xs - tot;
    #pragma unroll
    for (int j=0;j<16;j++) cdfl[j] += basev;
    float total = __shfl_sync(0xffffffffu, cdfl[15], 31);
    float invT  = 1.f/fmaxf(total, 1e-8f);
    // soft quantiles
    float gv0 = mnA;
    #pragma unroll
    for (int j=0;j<16;j++) cdfl[j] *= invT;
    for (int q=0;q<NQ;q++){
        float qq = q*(1.f/19.f);
        float sw=0.f, swg=0.f;
        #pragma unroll
        for (int j=0;j<16;j++){
            int p = pbase + j;
            if (p < GRID_PTS){
                float dist = fabsf(cdfl[j] - qq);
                float wgt = __fdividef(1.f, 1.f + __expf(100.f*dist));
                sw += wgt;
                swg = fmaf(wgt, fmaf((float)p, step, gv0), swg);
            }
        }
        #pragma unroll
        for (int o=16;o;o>>=1){ sw  += __shfl_xor_sync(0xffffffffu,sw,o);
                                swg += __shfl_xor_sync(0xffffffffu,swg,o); }
        if (lane==0) g_kf[rg*2560 + d*NQ + q] = swg/(sw + 1e-8f);
    }
}

// ---------------- projections + (last block) final risk ----------------
__global__ void k_proj(const float* lpW0,const float* lpb0,const float* lpW1,const float* lpb1,
                       const float* lpW2,const float* lpb2,
                       const float* kW0,const float* kb0,const float* kW1,const float* kb1,
                       const float* kW2,const float* kb2,
                       const float* beta, const float* h0, float* out){
    int rg = blockIdx.x; int g = rg&3; int ro = rg>>2;
    const float* lpW = (ro==0)?lpW0:(ro==1)?lpW1:lpW2;
    const float* lpb = (ro==0)?lpb0:(ro==1)?lpb1:lpb2;
    const float* kW  = (ro==0)?kW0 :(ro==1)?kW1 :kW2;
    const float* kb  = (ro==0)?kb0 :(ro==1)?kb1 :kb2;
    int t = threadIdx.x; int o = t&31, seg = t>>5;
    const float* kf = &g_kf[rg*2560];
    float kp = 0.f;
    for (int i=seg*320; i<seg*320+320; i++)
        kp = fmaf(kf[i], kW[i*32 + o], kp);
    const float* wp = &g_pool[rg*DIM];
    float hp = 0.f;
    for (int dd=seg*16; dd<seg*16+16; dd++)
        hp = fmaf(wp[dd], lpW[dd*32 + o], hp);
    __shared__ float r1[256], r2s[256];
    __shared__ int slast;
    r1[t]=kp; r2s[t]=hp; __syncthreads();
    if (t < 32){
        float ks=0.f, hs=0.f;
        for (int s=0;s<8;s++){ ks += r1[t + s*32]; hs += r2s[t + s*32]; }
        float val = (ks + kb[t]) + (hs + lpb[t]);
        atomicAdd(&g_acc[g*32 + t], val*(1.f/3.f));
    }
    __threadfence();
    __syncthreads();
    if (t == 0){
        int prev = atomicAdd(&g_done, 1);
        slast = (prev == NRG-1);
    }
    __syncthreads();
    if (slast && t < 128){
        __threadfence();
        int gg = t>>5, oo = t&31;
        float vv = g_acc[gg*32 + oo]*beta[oo];
        #pragma unroll
        for (int ofs=16; ofs; ofs>>=1) vv += __shfl_xor_sync(0xffffffffu, vv, ofs);
        if (oo==0) out[gg] = vv + h0[0];
    }
}

// ---------------- launch ----------------
extern "C" void kernel_launch(void* const* d_in, const int* in_sizes, int n_in,
                              void* d_out, int out_size){
    const float* x   = (const float*)d_in[0];
    const int*   ei  = (const int*)d_in[1];
    const float* W0  = (const float*)d_in[3];
    const float* as0 = (const float*)d_in[4];
    const float* ad0 = (const float*)d_in[5];
    const float* b0  = (const float*)d_in[6];
    const float* W1  = (const float*)d_in[7];
    const float* as1 = (const float*)d_in[8];
    const float* ad1 = (const float*)d_in[9];
    const float* b1  = (const float*)d_in[10];
    const float* lpW0=(const float*)d_in[11]; const float* lpb0=(const float*)d_in[12];
    const float* lpW1=(const float*)d_in[13]; const float* lpb1=(const float*)d_in[14];
    const float* lpW2=(const float*)d_in[15]; const float* lpb2=(const float*)d_in[16];
    const float* kW0 =(const float*)d_in[17]; const float* kb0 =(const float*)d_in[18];
    const float* kW1 =(const float*)d_in[19]; const float* kb1 =(const float*)d_in[20];
    const float* kW2 =(const float*)d_in[21]; const float* kb2 =(const float*)d_in[22];
    const float* poolw=(const float*)d_in[23];
    const float* beta =(const float*)d_in[24];
    const float* h0   =(const float*)d_in[25];
    float* out = (float*)d_out;

    k_prep<<<64, 256>>>(x);
    k_fill<<<128, 256>>>(ei);

    k_lin<<<256, 128>>>(x, 0, W0, as0, ad0);
    k_att<<<N_NODES, 128>>>(b0, 0);
    k_lin<<<256, 128>>>(x, 1, W1, as1, ad1);
    k_att<<<N_NODES, 128>>>(b1, 1);

    k_densq<<<1536, 32>>>(poolw);
    k_proj <<<NRG, 256>>>(lpW0,lpb0,lpW1,lpb1,lpW2,lpb2,
                          kW0,kb0,kW1,kb1,kW2,kb2, beta, h0, out);
}